// round 16
// baseline (speedup 1.0000x reference)
#include <cuda_runtime.h>
#include <cuda_bf16.h>
#include <math.h>

// Problem constants
#define PB  32
#define PM  10
#define PN  1000
#define MN  1010          // M + N
#define PD  128
#define NODES_TOTAL (PB*MN*PD)   // 4,136,960

// Grid layout: [pre 480][node 1010][comb 704]
#define PRE_FOLD   160
#define PRE_AGENT  320
#define NPRE       (PRE_FOLD + PRE_AGENT)    // 480
#define NODE_BLKS  1010                      // 8 warps x 4 nodes
#define NODE_START NPRE                      // 480
#define JPW 6
#define JPB (8*JPW)                          // 48 j's per comb block
#define JTILES ((MN + JPB - 1) / JPB)        // 22
#define COMB_BLKS (JTILES*PB)                // 704
#define COMB_START (NODE_START + NODE_BLKS)  // 1490
#define GRID_ALL  (COMB_START + COMB_BLKS)   // 2194

// Scratch (device globals — no allocation allowed)
__device__ __align__(16) float g_vpref[PD];      // Wp @ W_pref[:,0]
__device__ __align__(16) float g_Wnc[PD*5];      // Wn @ W_clients (128x5)
__device__ __align__(16) float g_Wna[PD*4];      // Wn @ W_agents  (128x4)
__device__ __align__(16) float g_A[PB*PM*PD];    // agent broadcast term (B*M x 128)
__device__ int g_done = 0;                       // pre-block completion counter
__device__ int g_exit = 0;                       // block exit counter (for reset)

// ---------------------------------------------------------------------------
// Single fused kernel. 2194 blocks x 256 threads.
// ---------------------------------------------------------------------------
__global__ void __launch_bounds__(256) k_all(
                      const float* __restrict__ Wpp,    // W_posproj (128x128)
                      const float* __restrict__ alpha,  // (1,)
                      const float* __restrict__ Wfin,   // W_final (128x384)
                      const float* __restrict__ Wpref,  // W_pref (128x1)
                      const float* __restrict__ Wc,     // W_clients (128x5)
                      const float* __restrict__ Wa,     // W_agents (128x4)
                      const float* __restrict__ locs,   // (B,1010,2)
                      const float* __restrict__ cap,    // (B,10)
                      const float* __restrict__ spd,    // (B,10)
                      const float* __restrict__ demand, // (B,1,1010)
                      const float* __restrict__ pref,   // (B,10,1010)
                      const float* __restrict__ Wdep,   // W_depot (128x2)
                      const float* __restrict__ Wda,    // W_depot_agents (128x256)
                      float* __restrict__ out)
{
    const int lane = threadIdx.x & 31;
    const int warp = threadIdx.x >> 5;    // 0..7
    const int d0   = lane * 4;
    const float2* locs2 = reinterpret_cast<const float2*>(locs);

    if (blockIdx.x < PRE_FOLD) {
        // =================== fold blocks ===================
        const int t = blockIdx.x * 8 + warp;
        float s = 0.f;
        if (t < 128) {
            const int d1 = t;
            #pragma unroll
            for (int q = 0; q < 4; q++) {
                int e = lane + 32 * q;
                s += Wfin[d1 * 384 + 128 + e] * Wpref[e];
            }
            #pragma unroll
            for (int o = 16; o; o >>= 1) s += __shfl_xor_sync(0xffffffffu, s, o);
            if (lane == 0) g_vpref[d1] = s;
        } else if (t < 768) {
            const int o = t - 128, d1 = o / 5, k = o % 5;
            #pragma unroll
            for (int q = 0; q < 4; q++) {
                int e = lane + 32 * q;
                s += Wfin[d1 * 384 + e] * __ldg(&Wc[e * 5 + k]);
            }
            #pragma unroll
            for (int off = 16; off; off >>= 1) s += __shfl_xor_sync(0xffffffffu, s, off);
            if (lane == 0) g_Wnc[o] = s;
        } else {
            const int o = t - 768, d1 = o / 4, k = o % 4;
            #pragma unroll
            for (int q = 0; q < 4; q++) {
                int e = lane + 32 * q;
                s += Wfin[d1 * 384 + e] * __ldg(&Wa[e * 4 + k]);
            }
            #pragma unroll
            for (int off = 16; off; off >>= 1) s += __shfl_xor_sync(0xffffffffu, s, off);
            if (lane == 0) g_Wna[o] = s;
        }
        // signal completion
        __syncthreads();
        if (threadIdx.x == 0) {
            __threadfence();
            atomicAdd(&g_done, 1);
        }
    } else if (blockIdx.x < NPRE) {
        // =================== A-chain blocks: one per (b, i) ===================
        const int idx = blockIdx.x - PRE_FOLD;     // 0..319
        const int b = idx / PM;
        const int i = idx % PM;
        const int tid = threadIdx.x;

        __shared__ float spe[PD], sde[PD], sae[PD], sdA[PD];

        const float lx = __ldg(&locs[(b * MN + i) * 2 + 0]);
        const float ly = __ldg(&locs[(b * MN + i) * 2 + 1]);
        const float c  = __ldg(&cap[b * PM + i]) * (1.0f / 40.0f);
        const float sp = __ldg(&spd[b * PM + i]);

        if (tid < PD) {
            sae[tid] = lx * Wa[tid * 4 + 0] + ly * Wa[tid * 4 + 1]
                     + c  * Wa[tid * 4 + 2] + sp * Wa[tid * 4 + 3];
            const float nl = -logf(10000.0f) / (float)PD;
            int k2 = (tid >> 1) * 2;
            float ang = (float)i * expf((float)k2 * nl);
            spe[tid] = (tid & 1) ? cosf(ang) : sinf(ang);
        }
        __syncthreads();

        const float a0 = __ldg(&alpha[0]);
        for (int r = 0; r < 16; r++) {
            int d1 = warp * 16 + r;
            float s = 0.f;
            #pragma unroll
            for (int q = 0; q < 4; q++) {
                int e = lane + 32 * q;
                s += spe[e] * Wpp[d1 * PD + e];
            }
            #pragma unroll
            for (int off = 16; off; off >>= 1) s += __shfl_xor_sync(0xffffffffu, s, off);
            if (lane == 0)
                sde[d1] = lx * Wdep[d1 * 2 + 0] + ly * Wdep[d1 * 2 + 1] + a0 * s;
        }
        __syncthreads();

        for (int r = 0; r < 16; r++) {
            int d1 = warp * 16 + r;
            float s = 0.f;
            #pragma unroll
            for (int q = 0; q < 4; q++) {
                int e = lane + 32 * q;
                s += sde[e] * Wda[d1 * 256 + e] + sae[e] * Wda[d1 * 256 + 128 + e];
            }
            #pragma unroll
            for (int off = 16; off; off >>= 1) s += __shfl_xor_sync(0xffffffffu, s, off);
            if (lane == 0) sdA[d1] = s;
        }
        __syncthreads();

        for (int r = 0; r < 16; r++) {
            int d1 = warp * 16 + r;
            float s = 0.f;
            #pragma unroll
            for (int q = 0; q < 4; q++) {
                int e = lane + 32 * q;
                s += sdA[e] * Wfin[d1 * 384 + 256 + e];
            }
            #pragma unroll
            for (int off = 16; off; off >>= 1) s += __shfl_xor_sync(0xffffffffu, s, off);
            if (lane == 0) g_A[(b * PM + i) * PD + d1] = s;
        }
        __syncthreads();
        if (threadIdx.x == 0) {
            __threadfence();
            atomicAdd(&g_done, 1);
        }
    } else if (blockIdx.x < COMB_START) {
        // =================== node blocks: inline features ===================
        const int n = blockIdx.x - NODE_START;         // 0..1009
        const int start = (n * 8 + warp) * 4;          // first node slot

        float wcl[4][5];
        #pragma unroll
        for (int r = 0; r < 4; r++)
            #pragma unroll
            for (int k = 0; k < 5; k++)
                wcl[r][k] = __ldg(&Wc[(d0 + r) * 5 + k]);

        #pragma unroll
        for (int u = 0; u < 4; u++) {
            const int gg = start + u;
            const int b  = gg / MN;
            const int j  = gg - b * MN;

            const float2 l = __ldg(&locs2[gg]);
            float ne[4];

            if (j < PM) {
                const float c  = __ldg(&cap[b * PM + j]) * (1.0f / 40.0f);
                const float sp = __ldg(&spd[b * PM + j]);
                #pragma unroll
                for (int r = 0; r < 4; r++) {
                    const int d = d0 + r;
                    ne[r] = l.x * __ldg(&Wa[d * 4 + 0]) + l.y * __ldg(&Wa[d * 4 + 1])
                          + c   * __ldg(&Wa[d * 4 + 2]) + sp  * __ldg(&Wa[d * 4 + 3]);
                }
            } else {
                const float2 dep = __ldg(&locs2[b * MN]);
                const float dx = l.x - dep.x;
                const float dy = l.y - dep.y;
                const float dist = sqrtf(dx * dx + dy * dy);
                const float ang  = atan2f(dy, dx);
                const float dem  = __ldg(&demand[gg]) * (1.0f / 40.0f);
                #pragma unroll
                for (int r = 0; r < 4; r++)
                    ne[r] = l.x * wcl[r][0] + l.y * wcl[r][1] + dem * wcl[r][2]
                          + dist * wcl[r][3] + ang * wcl[r][4];
            }

            __stcs(reinterpret_cast<float4*>(&out[gg * PD + d0]),
                   make_float4(ne[0], ne[1], ne[2], ne[3]));
        }
    } else {
        // =================== comb blocks: wait for pre, then stream ===========
        if (threadIdx.x == 0) {
            while (atomicAdd(&g_done, 0) < NPRE) __nanosleep(64);
        }
        __syncthreads();
        __threadfence();   // acquire: order subsequent loads after the flag

        const int cb = blockIdx.x - COMB_START;  // 0..703
        const int b  = cb & 31;
        const int jt = cb >> 5;

        // Register state — read through L2 (publication-safe)
        const float4 vp = __ldcg(reinterpret_cast<const float4*>(&g_vpref[d0]));

        float wnc[4][5];
        #pragma unroll
        for (int r = 0; r < 4; r++)
            #pragma unroll
            for (int k = 0; k < 5; k++)
                wnc[r][k] = __ldcg(&g_Wnc[(d0 + r) * 5 + k]);

        float4 a[PM];
        #pragma unroll
        for (int i = 0; i < PM; i++)
            a[i] = __ldcg(reinterpret_cast<const float4*>(&g_A[(b * PM + i) * PD + d0]));

        const float2 dep = __ldg(&locs2[b * MN]);
        float* __restrict__ out2 = out + NODES_TOTAL;
        const int jbase = jt * JPB + warp;     // first j for this warp (stride 8)

        if (jt < JTILES - 1) {
            // ---------- full tile: branch-free, pipelined ----------
            float2 lb;  float db;  float pb[PM];
            {
                const int nj = b * MN + jbase;
                lb = __ldg(&locs2[nj]);
                db = __ldg(&demand[nj]);
                #pragma unroll
                for (int i = 0; i < PM; i++)
                    pb[i] = __ldg(&pref[(b * PM + i) * MN + jbase]);
            }

            #pragma unroll
            for (int t = 0; t < JPW; t++) {
                const int j = jbase + 8 * t;

                const float lx = lb.x, ly = lb.y;
                const float dem = db * (1.0f / 40.0f);
                float p[PM];
                #pragma unroll
                for (int i = 0; i < PM; i++) p[i] = pb[i];

                if (t < JPW - 1) {
                    const int jn = j + 8;
                    const int njn = b * MN + jn;
                    lb = __ldg(&locs2[njn]);
                    db = __ldg(&demand[njn]);
                    #pragma unroll
                    for (int i = 0; i < PM; i++)
                        pb[i] = __ldg(&pref[(b * PM + i) * MN + jn]);
                }

                float nw[4];
                if (j < PM) {     // only possible in tile 0 (cold path)
                    const float c  = __ldg(&cap[b * PM + j]) * (1.0f / 40.0f);
                    const float sp = __ldg(&spd[b * PM + j]);
                    #pragma unroll
                    for (int r = 0; r < 4; r++) {
                        const int d = d0 + r;
                        nw[r] = lx * __ldcg(&g_Wna[d * 4 + 0]) + ly * __ldcg(&g_Wna[d * 4 + 1])
                              + c  * __ldcg(&g_Wna[d * 4 + 2]) + sp * __ldcg(&g_Wna[d * 4 + 3]);
                    }
                } else {
                    const float dx = lx - dep.x;
                    const float dy = ly - dep.y;
                    const float dist = sqrtf(dx * dx + dy * dy);
                    const float ang  = atan2f(dy, dx);
                    #pragma unroll
                    for (int r = 0; r < 4; r++)
                        nw[r] = lx * wnc[r][0] + ly * wnc[r][1] + dem * wnc[r][2]
                              + dist * wnc[r][3] + ang * wnc[r][4];
                }

                #pragma unroll
                for (int i = 0; i < PM; i++) {
                    float4 v;
                    v.x = nw[0] + p[i] * vp.x + a[i].x;
                    v.y = nw[1] + p[i] * vp.y + a[i].y;
                    v.z = nw[2] + p[i] * vp.z + a[i].z;
                    v.w = nw[3] + p[i] * vp.w + a[i].w;
                    __stcs(reinterpret_cast<float4*>(
                               &out2[((b * PM + i) * MN + j) * PD + d0]), v);
                }
            }
        } else {
            // ---------- tail tile: checked ----------
            #pragma unroll
            for (int t = 0; t < JPW; t++) {
                const int j = jbase + 8 * t;
                if (j >= MN) break;

                const int nj = b * MN + j;
                const float2 l = __ldg(&locs2[nj]);
                const float dem = __ldg(&demand[nj]) * (1.0f / 40.0f);
                const float dx = l.x - dep.x;
                const float dy = l.y - dep.y;
                const float dist = sqrtf(dx * dx + dy * dy);
                const float ang  = atan2f(dy, dx);

                float nw[4];
                #pragma unroll
                for (int r = 0; r < 4; r++)
                    nw[r] = l.x * wnc[r][0] + l.y * wnc[r][1] + dem * wnc[r][2]
                          + dist * wnc[r][3] + ang * wnc[r][4];

                float p[PM];
                #pragma unroll
                for (int i = 0; i < PM; i++)
                    p[i] = __ldg(&pref[(b * PM + i) * MN + j]);

                #pragma unroll
                for (int i = 0; i < PM; i++) {
                    float4 v;
                    v.x = nw[0] + p[i] * vp.x + a[i].x;
                    v.y = nw[1] + p[i] * vp.y + a[i].y;
                    v.z = nw[2] + p[i] * vp.z + a[i].z;
                    v.w = nw[3] + p[i] * vp.w + a[i].w;
                    __stcs(reinterpret_cast<float4*>(
                               &out2[((b * PM + i) * MN + j) * PD + d0]), v);
                }
            }
        }
    }

    // =================== exit protocol: last block resets counters ===========
    __syncthreads();
    if (threadIdx.x == 0) {
        int t = atomicAdd(&g_exit, 1);
        if (t == GRID_ALL - 1) {
            g_done = 0;
            g_exit = 0;
        }
    }
}

// ---------------------------------------------------------------------------
extern "C" void kernel_launch(void* const* d_in, const int* in_sizes, int n_in,
                              void* d_out, int out_size)
{
    const float* locs      = (const float*)d_in[0];
    const float* capacity  = (const float*)d_in[1];
    const float* speed     = (const float*)d_in[2];
    const float* demand    = (const float*)d_in[3];
    const float* pref      = (const float*)d_in[4];
    // d_in[5] = action_mask (bool) — unused
    const float* W_depot   = (const float*)d_in[6];
    const float* W_posproj = (const float*)d_in[7];
    const float* alpha     = (const float*)d_in[8];
    const float* W_agents  = (const float*)d_in[9];
    const float* W_da      = (const float*)d_in[10];
    const float* W_clients = (const float*)d_in[11];
    const float* W_pref    = (const float*)d_in[12];
    const float* W_final   = (const float*)d_in[13];
    float* out = (float*)d_out;

    k_all<<<GRID_ALL, 256>>>(W_posproj, alpha, W_final, W_pref, W_clients,
                             W_agents, locs, capacity, speed, demand, pref,
                             W_depot, W_da, out);
}

// round 17
// speedup vs baseline: 3.4114x; 3.4114x over previous
#include <cuda_runtime.h>
#include <cuda_bf16.h>
#include <math.h>

// Problem constants
#define PB  32
#define PM  10
#define PN  1000
#define MN  1010          // M + N
#define PD  128
#define NODES_TOTAL (PB*MN*PD)   // 4,136,960

// Launch 1 layout: [fold 160][A-chain 320][node 1010]
#define PRE_FOLD   160
#define PRE_AGENT  320
#define NPRE       (PRE_FOLD + PRE_AGENT)    // 480
#define NODE_BLKS  1010                      // 8 warps x 4 nodes
#define L1_BLKS    (NPRE + NODE_BLKS)        // 1490

// Launch 2 (comb) tiling
#define JPW 6
#define JPB (8*JPW)                          // 48 j's per comb block
#define JTILES ((MN + JPB - 1) / JPB)        // 22
#define COMB_BLKS (JTILES*PB)                // 704

// Scratch (device globals — no allocation allowed)
__device__ __align__(16) float g_vpref[PD];      // Wp @ W_pref[:,0]
__device__ __align__(16) float g_Wnc[PD*5];      // Wn @ W_clients (128x5)
__device__ __align__(16) float g_Wna[PD*4];      // Wn @ W_agents  (128x4)
__device__ __align__(16) float g_A[PB*PM*PD];    // agent broadcast term (B*M x 128)

// ---------------------------------------------------------------------------
// Launch 1: folds + A-chain + nodes-embedding rows. 1490 blocks x 256 thr.
// Pre blocks (0..479) start first; node blocks (480..1489) are independent
// and keep the SMs busy while the A-chain's latency chains drain.
// ---------------------------------------------------------------------------
__global__ void __launch_bounds__(256) k_l1(
                      const float* __restrict__ Wpp,    // W_posproj (128x128)
                      const float* __restrict__ alpha,  // (1,)
                      const float* __restrict__ Wfin,   // W_final (128x384)
                      const float* __restrict__ Wpref,  // W_pref (128x1)
                      const float* __restrict__ Wc,     // W_clients (128x5)
                      const float* __restrict__ Wa,     // W_agents (128x4)
                      const float* __restrict__ locs,   // (B,1010,2)
                      const float* __restrict__ cap,    // (B,10)
                      const float* __restrict__ spd,    // (B,10)
                      const float* __restrict__ demand, // (B,1,1010)
                      const float* __restrict__ Wdep,   // W_depot (128x2)
                      const float* __restrict__ Wda,    // W_depot_agents (128x256)
                      float* __restrict__ out)
{
    const int lane = threadIdx.x & 31;
    const int warp = threadIdx.x >> 5;    // 0..7
    const int d0   = lane * 4;
    const float2* locs2 = reinterpret_cast<const float2*>(locs);

    if (blockIdx.x >= NPRE) {
        // =================== node blocks: inline features ===================
        const int n = blockIdx.x - NPRE;               // 0..1009
        const int start = (n * 8 + warp) * 4;          // first node slot

        float wcl[4][5];
        #pragma unroll
        for (int r = 0; r < 4; r++)
            #pragma unroll
            for (int k = 0; k < 5; k++)
                wcl[r][k] = __ldg(&Wc[(d0 + r) * 5 + k]);

        #pragma unroll
        for (int u = 0; u < 4; u++) {
            const int gg = start + u;
            const int b  = gg / MN;
            const int j  = gg - b * MN;

            const float2 l = __ldg(&locs2[gg]);
            float ne[4];

            if (j < PM) {
                const float c  = __ldg(&cap[b * PM + j]) * (1.0f / 40.0f);
                const float sp = __ldg(&spd[b * PM + j]);
                #pragma unroll
                for (int r = 0; r < 4; r++) {
                    const int d = d0 + r;
                    ne[r] = l.x * __ldg(&Wa[d * 4 + 0]) + l.y * __ldg(&Wa[d * 4 + 1])
                          + c   * __ldg(&Wa[d * 4 + 2]) + sp  * __ldg(&Wa[d * 4 + 3]);
                }
            } else {
                const float2 dep = __ldg(&locs2[b * MN]);
                const float dx = l.x - dep.x;
                const float dy = l.y - dep.y;
                const float dist = sqrtf(dx * dx + dy * dy);
                const float ang  = atan2f(dy, dx);
                const float dem  = __ldg(&demand[gg]) * (1.0f / 40.0f);
                #pragma unroll
                for (int r = 0; r < 4; r++)
                    ne[r] = l.x * wcl[r][0] + l.y * wcl[r][1] + dem * wcl[r][2]
                          + dist * wcl[r][3] + ang * wcl[r][4];
            }

            __stcs(reinterpret_cast<float4*>(&out[gg * PD + d0]),
                   make_float4(ne[0], ne[1], ne[2], ne[3]));
        }
        return;
    }

    if (blockIdx.x < PRE_FOLD) {
        // =================== fold blocks ===================
        const int t = blockIdx.x * 8 + warp;
        float s = 0.f;
        if (t < 128) {
            const int d1 = t;
            #pragma unroll
            for (int q = 0; q < 4; q++) {
                int e = lane + 32 * q;
                s += Wfin[d1 * 384 + 128 + e] * Wpref[e];
            }
            #pragma unroll
            for (int o = 16; o; o >>= 1) s += __shfl_xor_sync(0xffffffffu, s, o);
            if (lane == 0) g_vpref[d1] = s;
        } else if (t < 768) {
            const int o = t - 128, d1 = o / 5, k = o % 5;
            #pragma unroll
            for (int q = 0; q < 4; q++) {
                int e = lane + 32 * q;
                s += Wfin[d1 * 384 + e] * __ldg(&Wc[e * 5 + k]);
            }
            #pragma unroll
            for (int off = 16; off; off >>= 1) s += __shfl_xor_sync(0xffffffffu, s, off);
            if (lane == 0) g_Wnc[o] = s;
        } else {
            const int o = t - 768, d1 = o / 4, k = o % 4;
            #pragma unroll
            for (int q = 0; q < 4; q++) {
                int e = lane + 32 * q;
                s += Wfin[d1 * 384 + e] * __ldg(&Wa[e * 4 + k]);
            }
            #pragma unroll
            for (int off = 16; off; off >>= 1) s += __shfl_xor_sync(0xffffffffu, s, off);
            if (lane == 0) g_Wna[o] = s;
        }
        return;
    }

    // =================== A-chain blocks: one per (b, i) ===================
    {
        const int idx = blockIdx.x - PRE_FOLD;     // 0..319
        const int b = idx / PM;
        const int i = idx % PM;
        const int tid = threadIdx.x;

        __shared__ float spe[PD], sde[PD], sae[PD], sdA[PD];

        const float lx = __ldg(&locs[(b * MN + i) * 2 + 0]);
        const float ly = __ldg(&locs[(b * MN + i) * 2 + 1]);
        const float c  = __ldg(&cap[b * PM + i]) * (1.0f / 40.0f);
        const float sp = __ldg(&spd[b * PM + i]);

        if (tid < PD) {
            sae[tid] = lx * Wa[tid * 4 + 0] + ly * Wa[tid * 4 + 1]
                     + c  * Wa[tid * 4 + 2] + sp * Wa[tid * 4 + 3];
            const float nl = -logf(10000.0f) / (float)PD;
            int k2 = (tid >> 1) * 2;
            float ang = (float)i * expf((float)k2 * nl);
            spe[tid] = (tid & 1) ? cosf(ang) : sinf(ang);
        }
        __syncthreads();

        const float a0 = __ldg(&alpha[0]);
        for (int r = 0; r < 16; r++) {
            int d1 = warp * 16 + r;
            float s = 0.f;
            #pragma unroll
            for (int q = 0; q < 4; q++) {
                int e = lane + 32 * q;
                s += spe[e] * Wpp[d1 * PD + e];
            }
            #pragma unroll
            for (int off = 16; off; off >>= 1) s += __shfl_xor_sync(0xffffffffu, s, off);
            if (lane == 0)
                sde[d1] = lx * Wdep[d1 * 2 + 0] + ly * Wdep[d1 * 2 + 1] + a0 * s;
        }
        __syncthreads();

        for (int r = 0; r < 16; r++) {
            int d1 = warp * 16 + r;
            float s = 0.f;
            #pragma unroll
            for (int q = 0; q < 4; q++) {
                int e = lane + 32 * q;
                s += sde[e] * Wda[d1 * 256 + e] + sae[e] * Wda[d1 * 256 + 128 + e];
            }
            #pragma unroll
            for (int off = 16; off; off >>= 1) s += __shfl_xor_sync(0xffffffffu, s, off);
            if (lane == 0) sdA[d1] = s;
        }
        __syncthreads();

        for (int r = 0; r < 16; r++) {
            int d1 = warp * 16 + r;
            float s = 0.f;
            #pragma unroll
            for (int q = 0; q < 4; q++) {
                int e = lane + 32 * q;
                s += sdA[e] * Wfin[d1 * 384 + 256 + e];
            }
            #pragma unroll
            for (int off = 16; off; off >>= 1) s += __shfl_xor_sync(0xffffffffu, s, off);
            if (lane == 0) g_A[(b * PM + i) * PD + d1] = s;
        }
    }
}

// ---------------------------------------------------------------------------
// Launch 2: comb-only. grid = 704 blocks x 256 threads, one warp per j row,
// pipelined, features inline. (R16 comb section, sync machinery removed.)
// ---------------------------------------------------------------------------
__global__ void __launch_bounds__(256) k_comb(
                       const float* __restrict__ locs,    // (B,1010,2)
                       const float* __restrict__ cap,     // (B,10)
                       const float* __restrict__ spd,     // (B,10)
                       const float* __restrict__ demand,  // (B,1,1010)
                       const float* __restrict__ pref,    // (B,10,1010)
                       float* __restrict__ out)
{
    const int lane = threadIdx.x & 31;
    const int warp = threadIdx.x >> 5;
    const int d0   = lane * 4;

    const int b  = blockIdx.x & 31;
    const int jt = blockIdx.x >> 5;

    const float2* locs2 = reinterpret_cast<const float2*>(locs);

    const float4 vp = *reinterpret_cast<const float4*>(&g_vpref[d0]);

    float wnc[4][5];
    #pragma unroll
    for (int r = 0; r < 4; r++)
        #pragma unroll
        for (int k = 0; k < 5; k++)
            wnc[r][k] = g_Wnc[(d0 + r) * 5 + k];

    float4 a[PM];
    #pragma unroll
    for (int i = 0; i < PM; i++)
        a[i] = *reinterpret_cast<const float4*>(&g_A[(b * PM + i) * PD + d0]);

    const float2 dep = __ldg(&locs2[b * MN]);
    float* __restrict__ out2 = out + NODES_TOTAL;
    const int jbase = jt * JPB + warp;     // first j for this warp (stride 8)

    if (jt < JTILES - 1) {
        // ---------- full tile: branch-free, pipelined ----------
        float2 lb;  float db;  float pb[PM];
        {
            const int nj = b * MN + jbase;
            lb = __ldg(&locs2[nj]);
            db = __ldg(&demand[nj]);
            #pragma unroll
            for (int i = 0; i < PM; i++)
                pb[i] = __ldg(&pref[(b * PM + i) * MN + jbase]);
        }

        #pragma unroll
        for (int t = 0; t < JPW; t++) {
            const int j = jbase + 8 * t;

            const float lx = lb.x, ly = lb.y;
            const float dem = db * (1.0f / 40.0f);
            float p[PM];
            #pragma unroll
            for (int i = 0; i < PM; i++) p[i] = pb[i];

            if (t < JPW - 1) {
                const int jn = j + 8;
                const int njn = b * MN + jn;
                lb = __ldg(&locs2[njn]);
                db = __ldg(&demand[njn]);
                #pragma unroll
                for (int i = 0; i < PM; i++)
                    pb[i] = __ldg(&pref[(b * PM + i) * MN + jn]);
            }

            float nw[4];
            if (j < PM) {     // only possible in tile 0 (cold path)
                const float c  = __ldg(&cap[b * PM + j]) * (1.0f / 40.0f);
                const float sp = __ldg(&spd[b * PM + j]);
                #pragma unroll
                for (int r = 0; r < 4; r++) {
                    const int d = d0 + r;
                    nw[r] = lx * g_Wna[d * 4 + 0] + ly * g_Wna[d * 4 + 1]
                          + c  * g_Wna[d * 4 + 2] + sp * g_Wna[d * 4 + 3];
                }
            } else {
                const float dx = lx - dep.x;
                const float dy = ly - dep.y;
                const float dist = sqrtf(dx * dx + dy * dy);
                const float ang  = atan2f(dy, dx);
                #pragma unroll
                for (int r = 0; r < 4; r++)
                    nw[r] = lx * wnc[r][0] + ly * wnc[r][1] + dem * wnc[r][2]
                          + dist * wnc[r][3] + ang * wnc[r][4];
            }

            #pragma unroll
            for (int i = 0; i < PM; i++) {
                float4 v;
                v.x = nw[0] + p[i] * vp.x + a[i].x;
                v.y = nw[1] + p[i] * vp.y + a[i].y;
                v.z = nw[2] + p[i] * vp.z + a[i].z;
                v.w = nw[3] + p[i] * vp.w + a[i].w;
                __stcs(reinterpret_cast<float4*>(
                           &out2[((b * PM + i) * MN + j) * PD + d0]), v);
            }
        }
    } else {
        // ---------- tail tile: checked ----------
        #pragma unroll
        for (int t = 0; t < JPW; t++) {
            const int j = jbase + 8 * t;
            if (j >= MN) break;

            const int nj = b * MN + j;
            const float2 l = __ldg(&locs2[nj]);
            const float dem = __ldg(&demand[nj]) * (1.0f / 40.0f);
            const float dx = l.x - dep.x;
            const float dy = l.y - dep.y;
            const float dist = sqrtf(dx * dx + dy * dy);
            const float ang  = atan2f(dy, dx);

            float nw[4];
            #pragma unroll
            for (int r = 0; r < 4; r++)
                nw[r] = l.x * wnc[r][0] + l.y * wnc[r][1] + dem * wnc[r][2]
                      + dist * wnc[r][3] + ang * wnc[r][4];

            float p[PM];
            #pragma unroll
            for (int i = 0; i < PM; i++)
                p[i] = __ldg(&pref[(b * PM + i) * MN + j]);

            #pragma unroll
            for (int i = 0; i < PM; i++) {
                float4 v;
                v.x = nw[0] + p[i] * vp.x + a[i].x;
                v.y = nw[1] + p[i] * vp.y + a[i].y;
                v.z = nw[2] + p[i] * vp.z + a[i].z;
                v.w = nw[3] + p[i] * vp.w + a[i].w;
                __stcs(reinterpret_cast<float4*>(
                           &out2[((b * PM + i) * MN + j) * PD + d0]), v);
            }
        }
    }
}

// ---------------------------------------------------------------------------
extern "C" void kernel_launch(void* const* d_in, const int* in_sizes, int n_in,
                              void* d_out, int out_size)
{
    const float* locs      = (const float*)d_in[0];
    const float* capacity  = (const float*)d_in[1];
    const float* speed     = (const float*)d_in[2];
    const float* demand    = (const float*)d_in[3];
    const float* pref      = (const float*)d_in[4];
    // d_in[5] = action_mask (bool) — unused
    const float* W_depot   = (const float*)d_in[6];
    const float* W_posproj = (const float*)d_in[7];
    const float* alpha     = (const float*)d_in[8];
    const float* W_agents  = (const float*)d_in[9];
    const float* W_da      = (const float*)d_in[10];
    const float* W_clients = (const float*)d_in[11];
    const float* W_pref    = (const float*)d_in[12];
    const float* W_final   = (const float*)d_in[13];
    float* out = (float*)d_out;

    k_l1<<<L1_BLKS, 256>>>(W_posproj, alpha, W_final, W_pref, W_clients,
                           W_agents, locs, capacity, speed, demand,
                           W_depot, W_da, out);

    k_comb<<<COMB_BLKS, 256>>>(locs, capacity, speed, demand, pref, out);
}